// round 2
// baseline (speedup 1.0000x reference)
#include <cuda_runtime.h>
#include <math.h>

// Problem constants
#define Dd   1024
#define Hn   16
#define HDd  64
#define Mm   1024
#define Kw   4
#define VDd  16
#define Bb   2
#define Ss   1024
#define Ww   1021          // (1024 - 4)/1 + 1
#define Cc   256           // H * VD
#define R1   (Bb * Ss)     // 2048 rows of q
#define R2   (Bb * Ww)     // 2042 rows of out

#define LP   1028          // padded logits row (1024 + 4) to dodge bank conflicts
#define RP   260           // padded reduction row

// Scratch (allocation-free rule: __device__ globals)
__device__ float g_q[R1 * Dd];            // 8 MB
__device__ float g_v[Bb * Ss * Cc];       // 2 MB  Vflat[b,t,h*16+v]

// ---------------- packed f32x2 helpers ----------------
__device__ __forceinline__ void FMA2(unsigned long long& c, unsigned long long a,
                                     unsigned long long b) {
    asm("fma.rn.f32x2 %0, %1, %2, %0;" : "+l"(c) : "l"(a), "l"(b));
}
__device__ __forceinline__ unsigned long long DUP2(float x) {
    unsigned long long r;
    asm("mov.b64 %0, {%1, %1};" : "=l"(r) : "f"(x));
    return r;
}
__device__ __forceinline__ unsigned long long PK2(float lo, float hi) {
    unsigned long long r;
    asm("mov.b64 %0, {%1, %2};" : "=l"(r) : "f"(lo), "f"(hi));
    return r;
}
__device__ __forceinline__ float2 UNPK(unsigned long long v) {
    float2 f;
    asm("mov.b64 {%0, %1}, %2;" : "=f"(f.x), "=f"(f.y) : "l"(v));
    return f;
}

// ======================================================================
// GEMM: C[r,n] = sum_k A[r,k] * W[n,k] + bias[n]
// MODE 0: A is dense (R x 1024) row-major
// MODE 1: A[r, j] gathered from Vflat: r=(b,w), j=(k,c) -> Vflat[b, w+k, c]
// Tile: BM=128, BN=64, BK=16, 256 threads, per-thread 8x4 (f32x2-packed)
// ======================================================================
template <int MODE>
__global__ void __launch_bounds__(256)
gemm_kernel(const float* __restrict__ A, const float* __restrict__ W,
            const float* __restrict__ bias, float* __restrict__ C, int Rrows)
{
    const int BM = 128, BN = 64, BK = 16;
    __shared__ float As[BK][BM + 4];
    __shared__ float Bs[BK][BN + 4];

    int tid = threadIdx.x;
    int tx = tid & 15;          // 16 column groups (4 cols each)
    int ty = tid >> 4;          // 16 row groups (8 rows each)
    int r0 = blockIdx.y * BM;
    int n0 = blockIdx.x * BN;

    unsigned long long acc[8][2];
#pragma unroll
    for (int i = 0; i < 8; i++) { acc[i][0] = 0ull; acc[i][1] = 0ull; }

    for (int k0 = 0; k0 < 1024; k0 += BK) {
        // ---- load A tile: 128x16 = 512 float4, 2 per thread ----
#pragma unroll
        for (int i = 0; i < 2; i++) {
            int f = tid + i * 256;
            int row = f >> 2;
            int kq = (f & 3) * 4;
            float4 v = make_float4(0.f, 0.f, 0.f, 0.f);
            int rr = r0 + row;
            if (rr < Rrows) {
                if (MODE == 0) {
                    v = *(const float4*)(A + (size_t)rr * 1024 + k0 + kq);
                } else {
                    int b = (rr >= Ww) ? 1 : 0;
                    int w = rr - b * Ww;
                    int j = k0 + kq;
                    int kk = j >> 8;      // which window offset (0..3)
                    int c  = j & 255;     // channel within token
                    v = *(const float4*)(A + ((size_t)(b * Ss + w + kk) * Cc) + c);
                }
            }
            As[kq + 0][row] = v.x; As[kq + 1][row] = v.y;
            As[kq + 2][row] = v.z; As[kq + 3][row] = v.w;
        }
        // ---- load B tile: 64x16 = 256 float4, 1 per thread ----
        {
            int col = tid >> 2;
            int kq = (tid & 3) * 4;
            float4 v = *(const float4*)(W + (size_t)(n0 + col) * 1024 + k0 + kq);
            Bs[kq + 0][col] = v.x; Bs[kq + 1][col] = v.y;
            Bs[kq + 2][col] = v.z; Bs[kq + 3][col] = v.w;
        }
        __syncthreads();

#pragma unroll
        for (int kk = 0; kk < BK; kk++) {
            float4 a0 = *(const float4*)&As[kk][ty * 8];
            float4 a1 = *(const float4*)&As[kk][ty * 8 + 4];
            float4 bf = *(const float4*)&Bs[kk][tx * 4];
            unsigned long long b0 = PK2(bf.x, bf.y);
            unsigned long long b1 = PK2(bf.z, bf.w);
            float av[8] = {a0.x, a0.y, a0.z, a0.w, a1.x, a1.y, a1.z, a1.w};
#pragma unroll
            for (int i = 0; i < 8; i++) {
                unsigned long long ad = DUP2(av[i]);
                FMA2(acc[i][0], ad, b0);
                FMA2(acc[i][1], ad, b1);
            }
        }
        __syncthreads();
    }

    int n = n0 + tx * 4;
    float4 bi = *(const float4*)(bias + n);
#pragma unroll
    for (int i = 0; i < 8; i++) {
        int rr = r0 + ty * 8 + i;
        if (rr < Rrows) {
            float2 c0 = UNPK(acc[i][0]);
            float2 c1 = UNPK(acc[i][1]);
            float4 ov = make_float4(c0.x + bi.x, c0.y + bi.y, c1.x + bi.z, c1.y + bi.w);
            *(float4*)(C + (size_t)rr * 1024 + n) = ov;
        }
    }
}

// ======================================================================
// Attention kernel: one block per (b, t). 256 threads.
// Phase 1: logits[h][m] = (q[b,t,h*64:]·Wk[m,:] + bk[m]) / 8  (f32x2 over m-pairs)
// Phase 2: per-head max + exp + sum (normalization deferred to epilogue)
// Phase 3: vals[h][v] = (sum_m e[h][m] * Wv[v][m]) / Z[h] + bv[v]
// ======================================================================
#define ATTN_SMEM_FLOATS (32 * LP + 2048 + 16 * RP + 16)
#define ATTN_SMEM_BYTES  (ATTN_SMEM_FLOATS * 4)

__global__ void __launch_bounds__(256, 1)
attn_kernel(const float* __restrict__ Wk, const float* __restrict__ bk,
            const float* __restrict__ Wv, const float* __restrict__ bv,
            const float* __restrict__ qbuf, float* __restrict__ vbuf)
{
    extern __shared__ float sm[];
    float* lg = sm;                                   // 16 * LP  logits->exp
    float* wv_s = sm + 16 * LP;                       // 16 * LP  Wv staged
    unsigned long long* qd = (unsigned long long*)(sm + 32 * LP); // 1024 dup'd q
    float* red = sm + 32 * LP + 2048;                 // 16 * RP  partial sums
    float* Z_s = red + 16 * RP;                       // 16

    int tid = threadIdx.x;
    int bt = blockIdx.x;                              // b*1024 + t
    const float* qrow = qbuf + (size_t)bt * 1024;

    // ---- stage q (duplicated pairs) and Wv into smem ----
    {
        float4 q4 = *(const float4*)(qrow + tid * 4);
        qd[tid * 4 + 0] = DUP2(q4.x);
        qd[tid * 4 + 1] = DUP2(q4.y);
        qd[tid * 4 + 2] = DUP2(q4.z);
        qd[tid * 4 + 3] = DUP2(q4.w);
    }
#pragma unroll
    for (int i = 0; i < 16; i++) {
        int idx = tid + i * 256;                      // 4096 float4s of Wv
        int vrow = idx >> 8;
        int m = (idx * 4) & 1023;
        float4 v4 = *(const float4*)(Wv + (size_t)idx * 4);
        *(float4*)&wv_s[vrow * LP + m] = v4;
    }
    __syncthreads();

    // ---- Phase 1: logits, packed along m (each thread owns m0, m0+1) ----
#pragma unroll 1
    for (int it = 0; it < 2; it++) {
        int m0 = (it * 256 + tid) * 2;
        const float* wkp = Wk + (size_t)m0 * 64;
        unsigned long long acc[16];
#pragma unroll
        for (int h = 0; h < 16; h++) acc[h] = 0ull;
#pragma unroll
        for (int eg = 0; eg < 16; eg++) {
            float4 w0 = *(const float4*)(wkp + eg * 4);
            float4 w1 = *(const float4*)(wkp + 64 + eg * 4);
            float w0a[4] = {w0.x, w0.y, w0.z, w0.w};
            float w1a[4] = {w1.x, w1.y, w1.z, w1.w};
#pragma unroll
            for (int j = 0; j < 4; j++) {
                unsigned long long wp = PK2(w0a[j], w1a[j]);
                int e = eg * 4 + j;
#pragma unroll
                for (int h = 0; h < 16; h++) {
                    FMA2(acc[h], qd[h * 64 + e], wp);   // LDS.64 broadcast
                }
            }
        }
        float bk0 = bk[m0], bk1 = bk[m0 + 1];
#pragma unroll
        for (int h = 0; h < 16; h++) {
            float2 c = UNPK(acc[h]);
            float2 o = make_float2((c.x + bk0) * 0.125f, (c.y + bk1) * 0.125f);
            *(float2*)&lg[h * LP + m0] = o;
        }
    }
    __syncthreads();

    // ---- Phase 2: softmax (max, exp, sum); 16 threads per head ----
    {
        int h = tid >> 4;
        int j = tid & 15;
        float* row = lg + h * LP;
        float mx = -INFINITY;
#pragma unroll
        for (int i = 0; i < 64; i++) mx = fmaxf(mx, row[j + i * 16]);
#pragma unroll
        for (int o = 8; o; o >>= 1)
            mx = fmaxf(mx, __shfl_xor_sync(0xffffffffu, mx, o, 16));
        float sum = 0.f;
#pragma unroll
        for (int i = 0; i < 64; i++) {
            float e = __expf(row[j + i * 16] - mx);
            row[j + i * 16] = e;
            sum += e;
        }
#pragma unroll
        for (int o = 8; o; o >>= 1)
            sum += __shfl_xor_sync(0xffffffffu, sum, o, 16);
        if (j == 0) Z_s[h] = sum;
    }
    __syncthreads();

    // ---- Phase 3: vals = e @ Wv^T, 4x4 register tile, f32x2 over m ----
    {
        int s = tid & 15;               // m-slice (interleaved: m = s*4 + g*64)
        int vg = (tid >> 4) & 3;        // v group
        int hg = tid >> 6;              // h group
        unsigned long long acc2[4][4];
#pragma unroll
        for (int i = 0; i < 4; i++)
#pragma unroll
            for (int j = 0; j < 4; j++) acc2[i][j] = 0ull;

#pragma unroll 4
        for (int g = 0; g < 16; g++) {
            int mo = s * 4 + g * 64;
            ulonglong2 av[4], wq[4];
#pragma unroll
            for (int i = 0; i < 4; i++)
                av[i] = *(const ulonglong2*)(lg + (hg * 4 + i) * LP + mo);
#pragma unroll
            for (int j = 0; j < 4; j++)
                wq[j] = *(const ulonglong2*)(wv_s + (vg * 4 + j) * LP + mo);
#pragma unroll
            for (int i = 0; i < 4; i++)
#pragma unroll
                for (int j = 0; j < 4; j++) {
                    FMA2(acc2[i][j], av[i].x, wq[j].x);
                    FMA2(acc2[i][j], av[i].y, wq[j].y);
                }
        }
#pragma unroll
        for (int i = 0; i < 4; i++)
#pragma unroll
            for (int j = 0; j < 4; j++) {
                float2 p = UNPK(acc2[i][j]);
                red[s * RP + (hg * 4 + i) * 16 + (vg * 4 + j)] = p.x + p.y;
            }
    }
    __syncthreads();

    // ---- epilogue: reduce over 16 slices, normalize, +bv, store Vflat ----
    {
        float ssum = 0.f;
#pragma unroll
        for (int s2 = 0; s2 < 16; s2++) ssum += red[s2 * RP + tid];
        int h = tid >> 4, v = tid & 15;
        float val = ssum / Z_s[h] + bv[v];
        vbuf[(size_t)bt * 256 + tid] = val;
    }
}

// ======================================================================
extern "C" void kernel_launch(void* const* d_in, const int* in_sizes, int n_in,
                              void* d_out, int out_size)
{
    const float* x  = (const float*)d_in[0];
    const float* Wq = (const float*)d_in[1];
    const float* bq = (const float*)d_in[2];
    const float* Wk = (const float*)d_in[3];
    const float* bk = (const float*)d_in[4];
    const float* Wv = (const float*)d_in[5];
    const float* bv = (const float*)d_in[6];
    const float* Wh = (const float*)d_in[7];
    const float* bh = (const float*)d_in[8];
    float* out = (float*)d_out;

    float* qbuf = nullptr;
    float* vbuf = nullptr;
    cudaGetSymbolAddress((void**)&qbuf, g_q);
    cudaGetSymbolAddress((void**)&vbuf, g_v);

    cudaFuncSetAttribute(attn_kernel,
                         cudaFuncAttributeMaxDynamicSharedMemorySize,
                         ATTN_SMEM_BYTES);

    // 1) q = x @ Wq^T + bq
    gemm_kernel<0><<<dim3(16, 16), 256>>>(x, Wq, bq, qbuf, R1);
    // 2) per-token attention -> Vflat
    attn_kernel<<<Bb * Ss, 256, ATTN_SMEM_BYTES>>>(Wk, bk, Wv, bv, qbuf, vbuf);
    // 3) out = gather(Vflat) @ Wh^T + bh
    gemm_kernel<1><<<dim3(16, 16), 256>>>(vbuf, Wh, bh, out, R2);
}

// round 3
// speedup vs baseline: 6.6337x; 6.6337x over previous
#include <cuda_runtime.h>
#include <math.h>

// Problem constants
#define Dd   1024
#define Hn   16
#define HDd  64
#define Mm   1024
#define Kw   4
#define VDd  16
#define Bb   2
#define Ss   1024
#define Ww   1021
#define Cc   256
#define R1   (Bb * Ss)
#define R2   (Bb * Ww)

// Scratch
__device__ float g_q[R1 * Dd];            // 8 MB
__device__ float g_v[Bb * Ss * Cc];       // 2 MB  Vflat[b,t,h*16+v]

// ---------------- packed f32x2 helpers ----------------
__device__ __forceinline__ void FMA2(unsigned long long& c, unsigned long long a,
                                     unsigned long long b) {
    asm("fma.rn.f32x2 %0, %1, %2, %0;" : "+l"(c) : "l"(a), "l"(b));
}
__device__ __forceinline__ unsigned long long DUP2(float x) {
    unsigned long long r;
    asm("mov.b64 %0, {%1, %1};" : "=l"(r) : "f"(x));
    return r;
}
__device__ __forceinline__ float2 UNPK(unsigned long long v) {
    float2 f;
    asm("mov.b64 {%0, %1}, %2;" : "=f"(f.x), "=f"(f.y) : "l"(v));
    return f;
}

// ======================================================================
// GEMM: C[r,n] = sum_k A[r,k] * W[n,k] + bias[n]
// MODE 0: dense A. MODE 1: A gathered from Vflat windows.
// BM=128, BN=64, BK=16, 256 threads, 8x4 per thread, row-paired f32x2 accs.
// ======================================================================
template <int MODE>
__global__ void __launch_bounds__(256)
gemm_kernel(const float* __restrict__ A, const float* __restrict__ W,
            const float* __restrict__ bias, float* __restrict__ C, int Rrows)
{
    const int BM = 128, BN = 64, BK = 16;
    __shared__ float As[BK][BM + 4];
    __shared__ float Bs[BK][BN + 4];

    int tid = threadIdx.x;
    int tx = tid & 15;
    int ty = tid >> 4;
    int r0 = blockIdx.y * BM;
    int n0 = blockIdx.x * BN;

    unsigned long long acc[4][4];   // [row-pair][n]
#pragma unroll
    for (int p = 0; p < 4; p++)
#pragma unroll
        for (int n = 0; n < 4; n++) acc[p][n] = 0ull;

    for (int k0 = 0; k0 < 1024; k0 += BK) {
#pragma unroll
        for (int i = 0; i < 2; i++) {
            int f = tid + i * 256;
            int row = f >> 2;
            int kq = (f & 3) * 4;
            float4 v = make_float4(0.f, 0.f, 0.f, 0.f);
            int rr = r0 + row;
            if (rr < Rrows) {
                if (MODE == 0) {
                    v = *(const float4*)(A + (size_t)rr * 1024 + k0 + kq);
                } else {
                    int b = (rr >= Ww) ? 1 : 0;
                    int w = rr - b * Ww;
                    int j = k0 + kq;
                    int kk = j >> 8;
                    int c  = j & 255;
                    v = *(const float4*)(A + ((size_t)(b * Ss + w + kk) * Cc) + c);
                }
            }
            As[kq + 0][row] = v.x; As[kq + 1][row] = v.y;
            As[kq + 2][row] = v.z; As[kq + 3][row] = v.w;
        }
        {
            int col = tid >> 2;
            int kq = (tid & 3) * 4;
            float4 v = *(const float4*)(W + (size_t)(n0 + col) * 1024 + k0 + kq);
            Bs[kq + 0][col] = v.x; Bs[kq + 1][col] = v.y;
            Bs[kq + 2][col] = v.z; Bs[kq + 3][col] = v.w;
        }
        __syncthreads();

#pragma unroll
        for (int kk = 0; kk < BK; kk++) {
            ulonglong2 a01 = *(const ulonglong2*)&As[kk][ty * 8];
            ulonglong2 a23 = *(const ulonglong2*)&As[kk][ty * 8 + 4];
            float4 bf = *(const float4*)&Bs[kk][tx * 4];
            unsigned long long ap[4] = {a01.x, a01.y, a23.x, a23.y};
            unsigned long long bd[4] = {DUP2(bf.x), DUP2(bf.y), DUP2(bf.z), DUP2(bf.w)};
#pragma unroll
            for (int p = 0; p < 4; p++)
#pragma unroll
                for (int n = 0; n < 4; n++)
                    FMA2(acc[p][n], ap[p], bd[n]);
        }
        __syncthreads();
    }

    int n = n0 + tx * 4;
    float4 bi = *(const float4*)(bias + n);
#pragma unroll
    for (int p = 0; p < 4; p++) {
        float2 c0 = UNPK(acc[p][0]);
        float2 c1 = UNPK(acc[p][1]);
        float2 c2 = UNPK(acc[p][2]);
        float2 c3 = UNPK(acc[p][3]);
        int row0 = r0 + ty * 8 + 2 * p;
        if (row0 < Rrows) {
            float4 o0 = make_float4(c0.x + bi.x, c1.x + bi.y, c2.x + bi.z, c3.x + bi.w);
            *(float4*)(C + (size_t)row0 * 1024 + n) = o0;
        }
        if (row0 + 1 < Rrows) {
            float4 o1 = make_float4(c0.y + bi.x, c1.y + bi.y, c2.y + bi.z, c3.y + bi.w);
            *(float4*)(C + (size_t)(row0 + 1) * 1024 + n) = o1;
        }
    }
}

// ======================================================================
// Flash-style attention. Block = 64 rows (4 tokens x 16 heads), 256 thr.
// m processed in 8 chunks of 128. Online softmax; vals accumulated with
// per-chunk rescale. 98.3 KB smem -> 2 CTAs/SM.
// ======================================================================
#define RB 64
#define TOK 4
#define MC 128
#define NCH 8

#define OFF_AS   0                    // [64][68]  q^T
#define OFF_BS   4352                 // [64][132] Wk^T chunk
#define OFF_ES   12800                // [64][140] exp tile
#define OFF_WV   21760                // [128][20] Wv^T chunk
#define OFF_BK   24320                // [128]
#define OFF_MR   24448                // [64] rescale mult per row
#define OFF_ZR   24512                // [64] Z per row
#define ATTN_SMEM_FLOATS 24576
#define ATTN_SMEM_BYTES  (ATTN_SMEM_FLOATS * 4)

__global__ void __launch_bounds__(256, 2)
attn_kernel(const float* __restrict__ Wk, const float* __restrict__ bk,
            const float* __restrict__ Wv, const float* __restrict__ bv,
            const float* __restrict__ qbuf, float* __restrict__ vbuf)
{
    extern __shared__ float sm[];
    float* As   = sm + OFF_AS;
    float* Bs   = sm + OFF_BS;
    float* Es   = sm + OFF_ES;
    float* WvsT = sm + OFF_WV;
    float* bks  = sm + OFF_BK;
    float* mrow = sm + OFF_MR;
    float* zrow = sm + OFF_ZR;

    int tid = threadIdx.x;
    int tx = tid & 15;
    int ty = tid >> 4;
    int bt0 = blockIdx.x * TOK;       // first global token (b*1024+t flattened)

    // val-phase identity
    int vrow = tid & 63;
    int vg   = tid >> 6;

    // ---- stage q transposed: As[e][lt*16+h] ----
#pragma unroll
    for (int i = 0; i < 4; i++) {
        int g = (tid + i * 256) * 4;
        int lt = g >> 10;
        int rem = g & 1023;           // h*64+e
        int h = rem >> 6;
        int e = rem & 63;
        float4 v = *(const float4*)(qbuf + (size_t)(bt0 + lt) * 1024 + rem);
        int r = lt * 16 + h;
        As[(e + 0) * 68 + r] = v.x;
        As[(e + 1) * 68 + r] = v.y;
        As[(e + 2) * 68 + r] = v.z;
        As[(e + 3) * 68 + r] = v.w;
    }

    float m_run[4], s_part[4];
#pragma unroll
    for (int i = 0; i < 4; i++) { m_run[i] = -INFINITY; s_part[i] = 0.f; }
    float va[4] = {0.f, 0.f, 0.f, 0.f};

    __syncthreads();   // As ready (also covers first-chunk staging hazards)

    for (int ch = 0; ch < NCH; ch++) {
        int m0 = ch * MC;

        // ---- stage Wk chunk: Bs[e][ml] ----
#pragma unroll
        for (int i = 0; i < 8; i++) {
            int idx = tid + i * 256;
            int ml = idx >> 4;
            int e4 = (idx & 15) * 4;
            float4 v = *(const float4*)(Wk + (size_t)(m0 + ml) * 64 + e4);
            Bs[(e4 + 0) * 132 + ml] = v.x;
            Bs[(e4 + 1) * 132 + ml] = v.y;
            Bs[(e4 + 2) * 132 + ml] = v.z;
            Bs[(e4 + 3) * 132 + ml] = v.w;
        }
        // ---- stage Wv chunk transposed: WvsT[ml][v] ----
#pragma unroll
        for (int i = 0; i < 2; i++) {
            int idx = tid + i * 256;
            int v = idx >> 5;
            int ml4 = (idx & 31) * 4;
            float4 w = *(const float4*)(Wv + (size_t)v * 1024 + m0 + ml4);
            WvsT[(ml4 + 0) * 20 + v] = w.x;
            WvsT[(ml4 + 1) * 20 + v] = w.y;
            WvsT[(ml4 + 2) * 20 + v] = w.z;
            WvsT[(ml4 + 3) * 20 + v] = w.w;
        }
        if (tid < 32) {
            float4 b4 = *(const float4*)(bk + m0 + tid * 4);
            bks[tid * 4 + 0] = b4.x; bks[tid * 4 + 1] = b4.y;
            bks[tid * 4 + 2] = b4.z; bks[tid * 4 + 3] = b4.w;
        }
        __syncthreads();

        // ---- GEMM tile: 64 rows x 128 m, K=64; thread: 4r x 8m ----
        unsigned long long acc[4][4];   // [row][m-pair]
#pragma unroll
        for (int i = 0; i < 4; i++)
#pragma unroll
            for (int j = 0; j < 4; j++) acc[i][j] = 0ull;

#pragma unroll 4
        for (int e = 0; e < 64; e++) {
            float4 a = *(const float4*)&As[e * 68 + ty * 4];
            ulonglong2 b01 = *(const ulonglong2*)&Bs[e * 132 + tx * 8];
            ulonglong2 b23 = *(const ulonglong2*)&Bs[e * 132 + tx * 8 + 4];
            unsigned long long bp[4] = {b01.x, b01.y, b23.x, b23.y};
            unsigned long long ad[4] = {DUP2(a.x), DUP2(a.y), DUP2(a.z), DUP2(a.w)};
#pragma unroll
            for (int i = 0; i < 4; i++)
#pragma unroll
                for (int j = 0; j < 4; j++)
                    FMA2(acc[i][j], ad[i], bp[j]);
        }

        // ---- per-row online softmax stats + exp tile ----
#pragma unroll
        for (int i = 0; i < 4; i++) {
            int r = ty * 4 + i;
            float lgv[8];
#pragma unroll
            for (int j = 0; j < 4; j++) {
                float2 c = UNPK(acc[i][j]);
                lgv[2 * j + 0] = (c.x + bks[tx * 8 + 2 * j + 0]) * 0.125f;
                lgv[2 * j + 1] = (c.y + bks[tx * 8 + 2 * j + 1]) * 0.125f;
            }
            float cm = lgv[0];
#pragma unroll
            for (int k = 1; k < 8; k++) cm = fmaxf(cm, lgv[k]);
#pragma unroll
            for (int o = 8; o; o >>= 1)
                cm = fmaxf(cm, __shfl_xor_sync(0xffffffffu, cm, o, 16));
            float mn = fmaxf(m_run[i], cm);
            float mult = __expf(m_run[i] - mn);
            m_run[i] = mn;
            float csum = 0.f;
#pragma unroll
            for (int k = 0; k < 8; k++) {
                float ev = __expf(lgv[k] - mn);
                csum += ev;
                Es[r * 140 + tx * 8 + k] = ev;
            }
            s_part[i] = s_part[i] * mult + csum;
            if (tx == 0) mrow[r] = mult;
        }
        __syncthreads();

        // ---- val accumulation: thread (vrow, vg), 4 v over 128 m ----
        {
            float mult = mrow[vrow];
            va[0] *= mult; va[1] *= mult; va[2] *= mult; va[3] *= mult;
            unsigned long long p01 = 0ull, p23 = 0ull;
#pragma unroll 4
            for (int mg = 0; mg < 32; mg++) {
                int ml = mg * 4;
                float4 ev = *(const float4*)&Es[vrow * 140 + ml];
                ulonglong2 w0 = *(const ulonglong2*)&WvsT[(ml + 0) * 20 + vg * 4];
                ulonglong2 w1 = *(const ulonglong2*)&WvsT[(ml + 1) * 20 + vg * 4];
                ulonglong2 w2 = *(const ulonglong2*)&WvsT[(ml + 2) * 20 + vg * 4];
                ulonglong2 w3 = *(const ulonglong2*)&WvsT[(ml + 3) * 20 + vg * 4];
                unsigned long long e0 = DUP2(ev.x), e1 = DUP2(ev.y);
                unsigned long long e2 = DUP2(ev.z), e3 = DUP2(ev.w);
                FMA2(p01, e0, w0.x); FMA2(p23, e0, w0.y);
                FMA2(p01, e1, w1.x); FMA2(p23, e1, w1.y);
                FMA2(p01, e2, w2.x); FMA2(p23, e2, w2.y);
                FMA2(p01, e3, w3.x); FMA2(p23, e3, w3.y);
            }
            float2 f01 = UNPK(p01);
            float2 f23 = UNPK(p23);
            va[0] += f01.x; va[1] += f01.y; va[2] += f23.x; va[3] += f23.y;
        }
        __syncthreads();   // protect Es/WvsT/Bs before next staging
    }

    // ---- finalize Z per row ----
#pragma unroll
    for (int i = 0; i < 4; i++) {
        float s = s_part[i];
#pragma unroll
        for (int o = 8; o; o >>= 1)
            s += __shfl_xor_sync(0xffffffffu, s, o, 16);
        if (tx == 0) zrow[ty * 4 + i] = s;
    }
    __syncthreads();

    // ---- output ----
    {
        float Z = zrow[vrow];
        float inv = 1.0f / Z;
        int lt = vrow >> 4;
        int h = vrow & 15;
        float4 o;
        o.x = va[0] * inv + bv[vg * 4 + 0];
        o.y = va[1] * inv + bv[vg * 4 + 1];
        o.z = va[2] * inv + bv[vg * 4 + 2];
        o.w = va[3] * inv + bv[vg * 4 + 3];
        *(float4*)(vbuf + (size_t)(bt0 + lt) * 256 + h * 16 + vg * 4) = o;
    }
}

// ======================================================================
extern "C" void kernel_launch(void* const* d_in, const int* in_sizes, int n_in,
                              void* d_out, int out_size)
{
    const float* x  = (const float*)d_in[0];
    const float* Wq = (const float*)d_in[1];
    const float* bq = (const float*)d_in[2];
    const float* Wk = (const float*)d_in[3];
    const float* bk = (const float*)d_in[4];
    const float* Wv = (const float*)d_in[5];
    const float* bv = (const float*)d_in[6];
    const float* Wh = (const float*)d_in[7];
    const float* bh = (const float*)d_in[8];
    float* out = (float*)d_out;

    float* qbuf = nullptr;
    float* vbuf = nullptr;
    cudaGetSymbolAddress((void**)&qbuf, g_q);
    cudaGetSymbolAddress((void**)&vbuf, g_v);

    cudaFuncSetAttribute(attn_kernel,
                         cudaFuncAttributeMaxDynamicSharedMemorySize,
                         ATTN_SMEM_BYTES);

    gemm_kernel<0><<<dim3(16, 16), 256>>>(x, Wq, bq, qbuf, R1);
    attn_kernel<<<(Bb * Ss) / TOK, 256, ATTN_SMEM_BYTES>>>(Wk, bk, Wv, bv, qbuf, vbuf);
    gemm_kernel<1><<<dim3(16, 16), 256>>>(vbuf, Wh, bh, out, R2);
}